// round 6
// baseline (speedup 1.0000x reference)
#include <cuda_runtime.h>
#include <cuda_bf16.h>

#define SEQ    4096
#define HIDDEN 2048
#define NH     16
#define NKV    2
#define HD     256
#define RHALF  32
#define GQ     (NH / NKV)

// Scratch (device globals — no allocations allowed)
__device__ float g_q[(size_t)SEQ * NH * HD];     // 64 MB
__device__ float g_k[(size_t)SEQ * NKV * HD];    // 8 MB
__device__ float g_v[(size_t)SEQ * NKV * HD];    // 8 MB
__device__ float g_ctx[(size_t)SEQ * NH * HD];   // 64 MB

// ---------------------------------------------------------------------------
// Tiled fp32 GEMM: C[M,N] = A[M,K] @ B[K,N], all row-major.
// 64x64 block tile, BK=16, 256 threads, 4x4 microtile per thread.
// All problem dims here are multiples of 64/16, so no bounds checks.
// ---------------------------------------------------------------------------
__global__ void __launch_bounds__(256) gemm64(const float* __restrict__ A,
                                              const float* __restrict__ B,
                                              float* __restrict__ C,
                                              int M, int N, int K) {
    __shared__ float As[16][68];  // stored transposed: As[k][m]
    __shared__ float Bs[16][68];  // Bs[k][n]

    int tid = threadIdx.x;
    int tx = tid & 15;      // col group (4 cols each)
    int ty = tid >> 4;      // row group (4 rows each)
    int row0 = blockIdx.y * 64;
    int col0 = blockIdx.x * 64;

    int arow = tid >> 2;          // 0..63
    int acol = (tid & 3) << 2;    // 0,4,8,12
    int brow = tid >> 4;          // 0..15
    int bcol = (tid & 15) << 2;   // 0..60

    const float* Aptr = A + (size_t)(row0 + arow) * K + acol;
    const float* Bptr = B + (size_t)brow * N + col0 + bcol;

    float acc[4][4];
#pragma unroll
    for (int i = 0; i < 4; i++)
#pragma unroll
        for (int j = 0; j < 4; j++) acc[i][j] = 0.f;

    for (int k0 = 0; k0 < K; k0 += 16) {
        float4 a = *(const float4*)(Aptr + k0);
        As[acol + 0][arow] = a.x;
        As[acol + 1][arow] = a.y;
        As[acol + 2][arow] = a.z;
        As[acol + 3][arow] = a.w;
        float4 b = *(const float4*)(Bptr + (size_t)k0 * N);
        *(float4*)&Bs[brow][bcol] = b;
        __syncthreads();
#pragma unroll
        for (int k = 0; k < 16; k++) {
            float4 bv = *(float4*)&Bs[k][tx * 4];
            float av0 = As[k][ty * 4 + 0];
            float av1 = As[k][ty * 4 + 1];
            float av2 = As[k][ty * 4 + 2];
            float av3 = As[k][ty * 4 + 3];
            acc[0][0] += av0 * bv.x; acc[0][1] += av0 * bv.y; acc[0][2] += av0 * bv.z; acc[0][3] += av0 * bv.w;
            acc[1][0] += av1 * bv.x; acc[1][1] += av1 * bv.y; acc[1][2] += av1 * bv.z; acc[1][3] += av1 * bv.w;
            acc[2][0] += av2 * bv.x; acc[2][1] += av2 * bv.y; acc[2][2] += av2 * bv.z; acc[2][3] += av2 * bv.w;
            acc[3][0] += av3 * bv.x; acc[3][1] += av3 * bv.y; acc[3][2] += av3 * bv.z; acc[3][3] += av3 * bv.w;
        }
        __syncthreads();
    }

#pragma unroll
    for (int i = 0; i < 4; i++) {
        float4 out;
        out.x = acc[i][0]; out.y = acc[i][1]; out.z = acc[i][2]; out.w = acc[i][3];
        *(float4*)(C + (size_t)(row0 + ty * 4 + i) * N + col0 + tx * 4) = out;
    }
}

// ---------------------------------------------------------------------------
// Partial RoPE for Q (rotate first 64 dims: [:32]=x1*c-x2*s, [32:64]=x1*s+x2*c)
// ---------------------------------------------------------------------------
__global__ void rope_q_kernel(const float* __restrict__ cosb,
                              const float* __restrict__ sinb) {
    int idx = blockIdx.x * 256 + threadIdx.x;   // SEQ*NH*32 total
    int i = idx & 31;
    int h = (idx >> 5) & (NH - 1);
    int s = idx >> 9;
    float c = cosb[s * RHALF + i];
    float sn = sinb[s * RHALF + i];
    float* p = g_q + ((size_t)s * NH + h) * HD;
    float x1 = p[i], x2 = p[i + RHALF];
    p[i] = x1 * c - x2 * sn;
    p[i + RHALF] = x1 * sn + x2 * c;
}

// ---------------------------------------------------------------------------
// Fused: partial RoPE on K (in place) + copy rope'd K and raw V to d_out tail.
// One thread per (s, h, half-dim-pair-or-pass-chunk). Layout: threads 0..127
// cover the 256 dims of one (s,h) row: dims 0..31 are rotate pairs, the rest
// are pass-through copies. idx = ((s*NKV + h)*128 + t).
// ---------------------------------------------------------------------------
__global__ void rope_copy_k_v_kernel(const float* __restrict__ cosb,
                                     const float* __restrict__ sinb,
                                     float* __restrict__ out_k,
                                     float* __restrict__ out_v) {
    int idx = blockIdx.x * 256 + threadIdx.x;   // SEQ*NKV*128 total
    int t = idx & 127;
    int row = idx >> 7;          // (s*NKV + h)
    int s = row >> 1;
    size_t base = (size_t)row * HD;
    float* kp = g_k + base;
    float* ok = out_k + base;

    if (t < 32) {
        // rotate pair (t, t+32)
        float c = cosb[s * RHALF + t];
        float sn = sinb[s * RHALF + t];
        float x1 = kp[t], x2 = kp[t + RHALF];
        float r1 = x1 * c - x2 * sn;
        float r2 = x1 * sn + x2 * c;
        kp[t] = r1; kp[t + RHALF] = r2;
        ok[t] = r1; ok[t + RHALF] = r2;
    } else {
        // pass-through dims 64..255: 96 threads * 2 dims each
        int d = 64 + (t - 32) * 2;
        float2 x = *(const float2*)(kp + d);
        *(float2*)(ok + d) = x;
    }
    // V copy: 128 threads * 2 dims
    float2 v = *(const float2*)(g_v + base + t * 2);
    *(float2*)(out_v + base + t * 2) = v;
}

// ---------------------------------------------------------------------------
// Flash attention, causal, fp32. BQ=32 query rows per CTA, BKEY=64 keys/iter.
// Grid: (SEQ/32, NH), 256 threads. 1 CTA/SM due to 170KB smem.
// ---------------------------------------------------------------------------
#define BQ   32
#define BKEY 64
#define QSTR 257
#define KSTR 257
#define VSTR 260
#define SSTR 65

__global__ void __launch_bounds__(256) attn_kernel(float scale) {
    extern __shared__ float sm[];
    float* Qs = sm;                         // [BQ][QSTR]
    float* Ks = Qs + BQ * QSTR;             // [BKEY][KSTR]
    float* Vs = Ks + BKEY * KSTR;           // [BKEY][VSTR] (16B-aligned rows)
    float* Ss = Vs + BKEY * VSTR;           // [BQ][SSTR]
    float* mrow = Ss + BQ * SSTR;           // [BQ]
    float* lrow = mrow + BQ;                // [BQ]
    float* arow = lrow + BQ;                // [BQ]

    int qb = blockIdx.x;
    int h = blockIdx.y;
    int kvh = h / GQ;
    int tid = threadIdx.x;
    int tr = tid >> 5;   // 0..7  (4 rows each)
    int tc = tid & 31;   // 0..31 (used both for S cols and O cols)

    // Load Q tile [32][256]
    for (int t = tid; t < BQ * (HD / 4); t += 256) {
        int r = t >> 6;
        int d4 = (t & 63) << 2;
        float4 q4 = *(const float4*)(g_q + ((size_t)(qb * BQ + r) * NH + h) * HD + d4);
        float* dst = Qs + r * QSTR + d4;
        dst[0] = q4.x; dst[1] = q4.y; dst[2] = q4.z; dst[3] = q4.w;
    }
    if (tid < BQ) { mrow[tid] = -1e30f; lrow[tid] = 0.f; }

    float o[4][8];
#pragma unroll
    for (int i = 0; i < 4; i++)
#pragma unroll
        for (int j = 0; j < 8; j++) o[i][j] = 0.f;

    int nkb = (qb * BQ + BQ - 1) / BKEY + 1;
    for (int kb = 0; kb < nkb; kb++) {
        __syncthreads();  // protect Ks/Vs from previous-iter readers; also covers init
        // Load K/V tiles [64][256]
        for (int t = tid; t < BKEY * (HD / 4); t += 256) {
            int r = t >> 6;
            int d4 = (t & 63) << 2;
            size_t gidx = ((size_t)(kb * BKEY + r) * NKV + kvh) * HD + d4;
            float4 k4 = *(const float4*)(g_k + gidx);
            float* kd = Ks + r * KSTR + d4;
            kd[0] = k4.x; kd[1] = k4.y; kd[2] = k4.z; kd[3] = k4.w;
            float4 v4 = *(const float4*)(g_v + gidx);
            *(float4*)(Vs + r * VSTR + d4) = v4;
        }
        __syncthreads();

        // S = Q K^T : thread computes 4 rows (tr*4..) x 2 cols (tc*2..)
        float sacc[4][2];
#pragma unroll
        for (int i = 0; i < 4; i++) { sacc[i][0] = 0.f; sacc[i][1] = 0.f; }
        const float* qr = Qs + (tr * 4) * QSTR;
        const float* kc = Ks + (tc * 2) * KSTR;
#pragma unroll 4
        for (int d = 0; d < HD; d++) {
            float b0 = kc[d];
            float b1 = kc[KSTR + d];
#pragma unroll
            for (int i = 0; i < 4; i++) {
                float a = qr[i * QSTR + d];
                sacc[i][0] += a * b0;
                sacc[i][1] += a * b1;
            }
        }
        int qbase = qb * BQ + tr * 4;
        int kbase = kb * BKEY + tc * 2;
#pragma unroll
        for (int i = 0; i < 4; i++)
#pragma unroll
            for (int j = 0; j < 2; j++)
                Ss[(tr * 4 + i) * SSTR + tc * 2 + j] =
                    (kbase + j <= qbase + i) ? sacc[i][j] * scale : -1e30f;
        __syncthreads();

        // Online softmax bookkeeping: one thread per query row
        if (tid < BQ) {
            float m_old = mrow[tid];
            float mx = m_old;
            float* srow = Ss + tid * SSTR;
            for (int j = 0; j < BKEY; j++) mx = fmaxf(mx, srow[j]);
            float al = __expf(m_old - mx);
            float sum = 0.f;
            for (int j = 0; j < BKEY; j++) {
                float p = __expf(srow[j] - mx);
                srow[j] = p;
                sum += p;
            }
            mrow[tid] = mx;
            arow[tid] = al;
            lrow[tid] = lrow[tid] * al + sum;
        }
        __syncthreads();

        // Rescale accumulators and O += P @ V (cols tc*8..tc*8+7)
        float al4[4];
#pragma unroll
        for (int i = 0; i < 4; i++) al4[i] = arow[tr * 4 + i];
#pragma unroll
        for (int i = 0; i < 4; i++)
#pragma unroll
            for (int j = 0; j < 8; j++) o[i][j] *= al4[i];

        const float* vb = Vs + tc * 8;
#pragma unroll 8
        for (int kk = 0; kk < BKEY; kk++) {
            float4 v0 = *(const float4*)(vb + kk * VSTR);
            float4 v1 = *(const float4*)(vb + kk * VSTR + 4);
#pragma unroll
            for (int i = 0; i < 4; i++) {
                float p = Ss[(tr * 4 + i) * SSTR + kk];
                o[i][0] += p * v0.x; o[i][1] += p * v0.y;
                o[i][2] += p * v0.z; o[i][3] += p * v0.w;
                o[i][4] += p * v1.x; o[i][5] += p * v1.y;
                o[i][6] += p * v1.z; o[i][7] += p * v1.w;
            }
        }
    }

    float linv[4];
#pragma unroll
    for (int i = 0; i < 4; i++) linv[i] = 1.f / lrow[tr * 4 + i];
#pragma unroll
    for (int i = 0; i < 4; i++) {
        size_t base = ((size_t)(qb * BQ + tr * 4 + i) * NH + h) * HD + tc * 8;
#pragma unroll
        for (int j = 0; j < 8; j++) g_ctx[base + j] = o[i][j] * linv[i];
    }
}

// ---------------------------------------------------------------------------
// Launch
// ---------------------------------------------------------------------------
extern "C" void kernel_launch(void* const* d_in, const int* in_sizes, int n_in,
                              void* d_out, int out_size) {
    const float* hs   = (const float*)d_in[0];  // [1,4096,2048]
    const float* cosb = (const float*)d_in[1];  // [4096,32]
    const float* sinb = (const float*)d_in[2];  // [4096,32]
    // d_in[3] = attention_mask (pure causal, applied analytically)
    const float* wq = (const float*)d_in[4];    // [2048,4096]
    const float* wk = (const float*)d_in[5];    // [2048,512]
    const float* wv = (const float*)d_in[6];    // [2048,512]
    const float* wo = (const float*)d_in[7];    // [4096,2048]

    float* out   = (float*)d_out;
    float* out_o = out;                                    // [4096,2048]
    float* out_k = out + (size_t)SEQ * HIDDEN;             // [4096,2,256]
    float* out_v = out_k + (size_t)SEQ * NKV * HD;         // [4096,2,256]

    float *qp, *kp, *vp, *cp;
    cudaGetSymbolAddress((void**)&qp, g_q);
    cudaGetSymbolAddress((void**)&kp, g_k);
    cudaGetSymbolAddress((void**)&vp, g_v);
    cudaGetSymbolAddress((void**)&cp, g_ctx);

    // Projections
    gemm64<<<dim3((NH * HD) / 64, SEQ / 64), 256>>>(hs, wq, qp, SEQ, NH * HD, HIDDEN);
    gemm64<<<dim3((NKV * HD) / 64, SEQ / 64), 256>>>(hs, wk, kp, SEQ, NKV * HD, HIDDEN);
    gemm64<<<dim3((NKV * HD) / 64, SEQ / 64), 256>>>(hs, wv, vp, SEQ, NKV * HD, HIDDEN);

    // RoPE on Q; fused RoPE+copy for K, copy for V
    rope_q_kernel<<<(SEQ * NH * RHALF) / 256, 256>>>(cosb, sinb);
    rope_copy_k_v_kernel<<<(SEQ * NKV * 128) / 256, 256>>>(cosb, sinb, out_k, out_v);

    // Attention
    size_t smem = (size_t)(BQ * QSTR + BKEY * KSTR + BKEY * VSTR + BQ * SSTR + 3 * BQ) * sizeof(float);
    cudaFuncSetAttribute(attn_kernel, cudaFuncAttributeMaxDynamicSharedMemorySize, (int)smem);
    attn_kernel<<<dim3(SEQ / BQ, NH), 256, smem>>>(0.0625f);  // 256^-0.5

    // Output projection
    gemm64<<<dim3(HIDDEN / 64, SEQ / 64), 256>>>(cp, wo, out_o, SEQ, HIDDEN, NH * HD);
}

// round 9
// speedup vs baseline: 1.2271x; 1.2271x over previous
#include <cuda_runtime.h>
#include <cuda_bf16.h>
#include <cstdint>

#define SEQ    4096
#define HIDDEN 2048
#define NH     16
#define NKV    2
#define HD     256
#define RHALF  32
#define GQ     (NH / NKV)

// ---------------------------------------------------------------------------
// Scratch (device globals — no allocations allowed)
// ---------------------------------------------------------------------------
__device__ float g_q[(size_t)SEQ * NH * HD];       // 64 MB
__device__ float g_k[(size_t)SEQ * NKV * HD];      // 8 MB
__device__ float g_v[(size_t)SEQ * NKV * HD];      // 8 MB
__device__ float g_ctx[(size_t)SEQ * NH * HD];     // 64 MB

// bf16 hi/lo split operands for tensor-core GEMMs
__device__ __nv_bfloat16 g_hsh[(size_t)SEQ * HIDDEN];
__device__ __nv_bfloat16 g_hsl[(size_t)SEQ * HIDDEN];
__device__ __nv_bfloat16 g_ctxh[(size_t)SEQ * NH * HD];
__device__ __nv_bfloat16 g_ctxl[(size_t)SEQ * NH * HD];
__device__ __nv_bfloat16 g_wqth[(size_t)(NH * HD) * HIDDEN];   // [4096][2048]
__device__ __nv_bfloat16 g_wqtl[(size_t)(NH * HD) * HIDDEN];
__device__ __nv_bfloat16 g_wkth[(size_t)(NKV * HD) * HIDDEN];  // [512][2048]
__device__ __nv_bfloat16 g_wktl[(size_t)(NKV * HD) * HIDDEN];
__device__ __nv_bfloat16 g_wvth[(size_t)(NKV * HD) * HIDDEN];
__device__ __nv_bfloat16 g_wvtl[(size_t)(NKV * HD) * HIDDEN];
__device__ __nv_bfloat16 g_woth[(size_t)HIDDEN * (NH * HD)];   // [2048][4096]
__device__ __nv_bfloat16 g_wotl[(size_t)HIDDEN * (NH * HD)];

// ---------------------------------------------------------------------------
// mma.sync m16n8k16 bf16 -> fp32 (baseline-PTX tensor core path; no tcgen05)
// ---------------------------------------------------------------------------
__device__ __forceinline__ void mma16816(float c[4],
                                         uint32_t a0, uint32_t a1, uint32_t a2, uint32_t a3,
                                         uint32_t b0, uint32_t b1) {
    asm volatile(
        "mma.sync.aligned.m16n8k16.row.col.f32.bf16.bf16.f32 "
        "{%0,%1,%2,%3}, {%4,%5,%6,%7}, {%8,%9}, {%0,%1,%2,%3};"
        : "+f"(c[0]), "+f"(c[1]), "+f"(c[2]), "+f"(c[3])
        : "r"(a0), "r"(a1), "r"(a2), "r"(a3), "r"(b0), "r"(b1));
}

// ---------------------------------------------------------------------------
// Prep kernels: elementwise fp32 -> bf16 hi/lo split; tiled transpose+split.
// ---------------------------------------------------------------------------
__global__ void __launch_bounds__(256) split_hi_lo(const float* __restrict__ x,
                                                   __nv_bfloat16* __restrict__ hi,
                                                   __nv_bfloat16* __restrict__ lo) {
    int i = blockIdx.x * 256 + threadIdx.x;
    float4 v = ((const float4*)x)[i];
    __nv_bfloat16 h0 = __float2bfloat16(v.x), h1 = __float2bfloat16(v.y);
    __nv_bfloat16 h2 = __float2bfloat16(v.z), h3 = __float2bfloat16(v.w);
    __nv_bfloat16 l0 = __float2bfloat16(v.x - __bfloat162float(h0));
    __nv_bfloat16 l1 = __float2bfloat16(v.y - __bfloat162float(h1));
    __nv_bfloat16 l2 = __float2bfloat16(v.z - __bfloat162float(h2));
    __nv_bfloat16 l3 = __float2bfloat16(v.w - __bfloat162float(h3));
    uint2 hp, lp;
    hp.x = (uint32_t)__bfloat16_as_ushort(h0) | ((uint32_t)__bfloat16_as_ushort(h1) << 16);
    hp.y = (uint32_t)__bfloat16_as_ushort(h2) | ((uint32_t)__bfloat16_as_ushort(h3) << 16);
    lp.x = (uint32_t)__bfloat16_as_ushort(l0) | ((uint32_t)__bfloat16_as_ushort(l1) << 16);
    lp.y = (uint32_t)__bfloat16_as_ushort(l2) | ((uint32_t)__bfloat16_as_ushort(l3) << 16);
    ((uint2*)hi)[i] = hp;
    ((uint2*)lo)[i] = lp;
}

// W [K][N] fp32 -> WT_hi/lo [N][K] bf16 (32x32 smem tile transpose)
__global__ void __launch_bounds__(256) transpose_split(const float* __restrict__ w,
                                                       __nv_bfloat16* __restrict__ th,
                                                       __nv_bfloat16* __restrict__ tl,
                                                       int K, int N) {
    __shared__ float tile[32][33];
    int n0 = blockIdx.x * 32, k0 = blockIdx.y * 32;
    int tx = threadIdx.x & 31, ty = threadIdx.x >> 5;  // ty 0..7
#pragma unroll
    for (int i = 0; i < 32; i += 8)
        tile[ty + i][tx] = w[(size_t)(k0 + ty + i) * N + n0 + tx];
    __syncthreads();
#pragma unroll
    for (int i = 0; i < 32; i += 8) {
        float v = tile[tx][ty + i];   // = w[k0+tx][n0+ty+i]
        __nv_bfloat16 h = __float2bfloat16(v);
        __nv_bfloat16 l = __float2bfloat16(v - __bfloat162float(h));
        size_t o = (size_t)(n0 + ty + i) * K + k0 + tx;
        th[o] = h;
        tl[o] = l;
    }
}

// ---------------------------------------------------------------------------
// Tensor-core bf16x3 GEMM via mma.sync:
//   C[M,N] fp32 = A[M,K] @ Bt[N,K]^T,  D += Ah*Bh + Ah*Bl + Al*Bh
// CTA tile 128x128, BK=32. 8 warps (2 x 4), warp tile 64x32.
// All dims here are multiples of 128/32 — no bounds checks.
// ---------------------------------------------------------------------------
#define ASTR 40   // bf16 per smem row (32 + 8 pad) -> conflict-free pair loads

__global__ void __launch_bounds__(256) gemm_mma(
    const __nv_bfloat16* __restrict__ Ah, const __nv_bfloat16* __restrict__ Al,
    const __nv_bfloat16* __restrict__ Bh, const __nv_bfloat16* __restrict__ Bl,
    float* __restrict__ C, int M, int N, int K)
{
    __shared__ __nv_bfloat16 sAh[128 * ASTR];
    __shared__ __nv_bfloat16 sAl[128 * ASTR];
    __shared__ __nv_bfloat16 sBh[128 * ASTR];
    __shared__ __nv_bfloat16 sBl[128 * ASTR];

    int tid = threadIdx.x;
    int wid = tid >> 5, lane = tid & 31;
    int gr = lane >> 2, q = lane & 3;
    int warp_m = (wid >> 2) * 64;   // 0 or 64
    int warp_n = (wid & 3) * 32;    // 0,32,64,96
    int m0 = blockIdx.y * 128, n0 = blockIdx.x * 128;

    float acc[4][4][4];
#pragma unroll
    for (int mt = 0; mt < 4; mt++)
#pragma unroll
        for (int nt = 0; nt < 4; nt++)
#pragma unroll
            for (int r = 0; r < 4; r++) acc[mt][nt][r] = 0.f;

    for (int k0 = 0; k0 < K; k0 += 32) {
        // Fill four [128][32] bf16 tiles; 512 16B-chunks each, 2 per thread.
#pragma unroll
        for (int i = 0; i < 2; i++) {
            int ch = tid + i * 256;            // 0..511
            int r = ch >> 2, c = (ch & 3) << 3;  // row, bf16-col (0,8,16,24)
            int so = r * ASTR + c;
            *(uint4*)(sAh + so) = *(const uint4*)(Ah + (size_t)(m0 + r) * K + k0 + c);
            *(uint4*)(sAl + so) = *(const uint4*)(Al + (size_t)(m0 + r) * K + k0 + c);
            *(uint4*)(sBh + so) = *(const uint4*)(Bh + (size_t)(n0 + r) * K + k0 + c);
            *(uint4*)(sBl + so) = *(const uint4*)(Bl + (size_t)(n0 + r) * K + k0 + c);
        }
        __syncthreads();

#pragma unroll
        for (int ks = 0; ks < 2; ks++) {       // two k16 halves of BK=32
            int kb = ks * 16 + 2 * q;
            // A fragments (hi & lo) for this warp's 4 m-tiles
            uint32_t ah[4][4], al[4][4];
#pragma unroll
            for (int mt = 0; mt < 4; mt++) {
                int row = warp_m + mt * 16 + gr;
                const __nv_bfloat16* bh_ = sAh + row * ASTR + kb;
                const __nv_bfloat16* bl_ = sAl + row * ASTR + kb;
                ah[mt][0] = *(const uint32_t*)bh_;
                ah[mt][1] = *(const uint32_t*)(bh_ + 8 * ASTR);
                ah[mt][2] = *(const uint32_t*)(bh_ + 8);
                ah[mt][3] = *(const uint32_t*)(bh_ + 8 * ASTR + 8);
                al[mt][0] = *(const uint32_t*)bl_;
                al[mt][1] = *(const uint32_t*)(bl_ + 8 * ASTR);
                al[mt][2] = *(const uint32_t*)(bl_ + 8);
                al[mt][3] = *(const uint32_t*)(bl_ + 8 * ASTR + 8);
            }
#pragma unroll
            for (int nt = 0; nt < 4; nt++) {
                int col = warp_n + nt * 8 + gr;
                const __nv_bfloat16* pbh = sBh + col * ASTR + kb;
                const __nv_bfloat16* pbl = sBl + col * ASTR + kb;
                uint32_t bh0 = *(const uint32_t*)pbh;
                uint32_t bh1 = *(const uint32_t*)(pbh + 8);
                uint32_t bl0 = *(const uint32_t*)pbl;
                uint32_t bl1 = *(const uint32_t*)(pbl + 8);
#pragma unroll
                for (int mt = 0; mt < 4; mt++) {
                    mma16816(acc[mt][nt], ah[mt][0], ah[mt][1], ah[mt][2], ah[mt][3], bh0, bh1);
                    mma16816(acc[mt][nt], ah[mt][0], ah[mt][1], ah[mt][2], ah[mt][3], bl0, bl1);
                    mma16816(acc[mt][nt], al[mt][0], al[mt][1], al[mt][2], al[mt][3], bh0, bh1);
                }
            }
        }
        __syncthreads();
    }

    // Epilogue: fragment layout (c0,c1)->(row gr, col 2q,2q+1); (c2,c3)->row gr+8
#pragma unroll
    for (int mt = 0; mt < 4; mt++) {
#pragma unroll
        for (int nt = 0; nt < 4; nt++) {
            int row = m0 + warp_m + mt * 16 + gr;
            int col = n0 + warp_n + nt * 8 + 2 * q;
            float2 v0 = make_float2(acc[mt][nt][0], acc[mt][nt][1]);
            float2 v1 = make_float2(acc[mt][nt][2], acc[mt][nt][3]);
            *(float2*)(C + (size_t)row * N + col) = v0;
            *(float2*)(C + (size_t)(row + 8) * N + col) = v1;
        }
    }
}

// ---------------------------------------------------------------------------
// Partial RoPE for Q (rotate first 64 dims: [:32]=x1*c-x2*s, [32:64]=x1*s+x2*c)
// ---------------------------------------------------------------------------
__global__ void rope_q_kernel(const float* __restrict__ cosb,
                              const float* __restrict__ sinb) {
    int idx = blockIdx.x * 256 + threadIdx.x;   // SEQ*NH*32 total
    int i = idx & 31;
    int h = (idx >> 5) & (NH - 1);
    int s = idx >> 9;
    float c = cosb[s * RHALF + i];
    float sn = sinb[s * RHALF + i];
    float* p = g_q + ((size_t)s * NH + h) * HD;
    float x1 = p[i], x2 = p[i + RHALF];
    p[i] = x1 * c - x2 * sn;
    p[i + RHALF] = x1 * sn + x2 * c;
}

// ---------------------------------------------------------------------------
// Fused: partial RoPE on K (in place) + copy rope'd K and raw V to d_out tail.
// ---------------------------------------------------------------------------
__global__ void rope_copy_k_v_kernel(const float* __restrict__ cosb,
                                     const float* __restrict__ sinb,
                                     float* __restrict__ out_k,
                                     float* __restrict__ out_v) {
    int idx = blockIdx.x * 256 + threadIdx.x;   // SEQ*NKV*128 total
    int t = idx & 127;
    int row = idx >> 7;          // (s*NKV + h)
    int s = row >> 1;
    size_t base = (size_t)row * HD;
    float* kp = g_k + base;
    float* ok = out_k + base;

    if (t < 32) {
        float c = cosb[s * RHALF + t];
        float sn = sinb[s * RHALF + t];
        float x1 = kp[t], x2 = kp[t + RHALF];
        float r1 = x1 * c - x2 * sn;
        float r2 = x1 * sn + x2 * c;
        kp[t] = r1; kp[t + RHALF] = r2;
        ok[t] = r1; ok[t + RHALF] = r2;
    } else {
        int d = 64 + (t - 32) * 2;
        float2 x = *(const float2*)(kp + d);
        *(float2*)(ok + d) = x;
    }
    float2 v = *(const float2*)(g_v + base + t * 2);
    *(float2*)(out_v + base + t * 2) = v;
}

// ---------------------------------------------------------------------------
// Flash attention, causal, fp32. BQ=32, BKEY=64. Grid (SEQ/32, NH), 256 thr.
// ---------------------------------------------------------------------------
#define BQ   32
#define BKEY 64
#define QSTR 257
#define KSTR 257
#define VSTR 260
#define SSTR 65

__global__ void __launch_bounds__(256) attn_kernel(float scale) {
    extern __shared__ float sm[];
    float* Qs = sm;
    float* Ks = Qs + BQ * QSTR;
    float* Vs = Ks + BKEY * KSTR;
    float* Ss = Vs + BKEY * VSTR;
    float* mrow = Ss + BQ * SSTR;
    float* lrow = mrow + BQ;
    float* arow = lrow + BQ;

    int qb = blockIdx.x;
    int h = blockIdx.y;
    int kvh = h / GQ;
    int tid = threadIdx.x;
    int tr = tid >> 5;
    int tc = tid & 31;

    for (int t = tid; t < BQ * (HD / 4); t += 256) {
        int r = t >> 6;
        int d4 = (t & 63) << 2;
        float4 q4 = *(const float4*)(g_q + ((size_t)(qb * BQ + r) * NH + h) * HD + d4);
        float* dst = Qs + r * QSTR + d4;
        dst[0] = q4.x; dst[1] = q4.y; dst[2] = q4.z; dst[3] = q4.w;
    }
    if (tid < BQ) { mrow[tid] = -1e30f; lrow[tid] = 0.f; }

    float o[4][8];
#pragma unroll
    for (int i = 0; i < 4; i++)
#pragma unroll
        for (int j = 0; j < 8; j++) o[i][j] = 0.f;

    int nkb = (qb * BQ + BQ - 1) / BKEY + 1;
    for (int kb = 0; kb < nkb; kb++) {
        __syncthreads();
        for (int t = tid; t < BKEY * (HD / 4); t += 256) {
            int r = t >> 6;
            int d4 = (t & 63) << 2;
            size_t gidx = ((size_t)(kb * BKEY + r) * NKV + kvh) * HD + d4;
            float4 k4 = *(const float4*)(g_k + gidx);
            float* kd = Ks + r * KSTR + d4;
            kd[0] = k4.x; kd[1] = k4.y; kd[2] = k4.z; kd[3] = k4.w;
            float4 v4 = *(const float4*)(g_v + gidx);
            *(float4*)(Vs + r * VSTR + d4) = v4;
        }
        __syncthreads();

        float sacc[4][2];
#pragma unroll
        for (int i = 0; i < 4; i++) { sacc[i][0] = 0.f; sacc[i][1] = 0.f; }
        const float* qr = Qs + (tr * 4) * QSTR;
        const float* kc = Ks + (tc * 2) * KSTR;
#pragma unroll 4
        for (int d = 0; d < HD; d++) {
            float b0 = kc[d];
            float b1 = kc[KSTR + d];
#pragma unroll
            for (int i = 0; i < 4; i++) {
                float a = qr[i * QSTR + d];
                sacc[i][0] += a * b0;
                sacc[i][1] += a * b1;
            }
        }
        int qbase = qb * BQ + tr * 4;
        int kbase = kb * BKEY + tc * 2;
#pragma unroll
        for (int i = 0; i < 4; i++)
#pragma unroll
            for (int j = 0; j < 2; j++)
                Ss[(tr * 4 + i) * SSTR + tc * 2 + j] =
                    (kbase + j <= qbase + i) ? sacc[i][j] * scale : -1e30f;
        __syncthreads();

        if (tid < BQ) {
            float m_old = mrow[tid];
            float mx = m_old;
            float* srow = Ss + tid * SSTR;
            for (int j = 0; j < BKEY; j++) mx = fmaxf(mx, srow[j]);
            float al = __expf(m_old - mx);
            float sum = 0.f;
            for (int j = 0; j < BKEY; j++) {
                float p = __expf(srow[j] - mx);
                srow[j] = p;
                sum += p;
            }
            mrow[tid] = mx;
            arow[tid] = al;
            lrow[tid] = lrow[tid] * al + sum;
        }
        __syncthreads();

        float al4[4];
#pragma unroll
        for (int i = 0; i < 4; i++) al4[i] = arow[tr * 4 + i];
#pragma unroll
        for (int i = 0; i < 4; i++)
#pragma unroll
            for (int j = 0; j < 8; j++) o[i][j] *= al4[i];

        const float* vb = Vs + tc * 8;
#pragma unroll 8
        for (int kk = 0; kk < BKEY; kk++) {
            float4 v0 = *(const float4*)(vb + kk * VSTR);
            float4 v1 = *(const float4*)(vb + kk * VSTR + 4);
#pragma unroll
            for (int i = 0; i < 4; i++) {
                float p = Ss[(tr * 4 + i) * SSTR + kk];
                o[i][0] += p * v0.x; o[i][1] += p * v0.y;
                o[i][2] += p * v0.z; o[i][3] += p * v0.w;
                o[i][4] += p * v1.x; o[i][5] += p * v1.y;
                o[i][6] += p * v1.z; o[i][7] += p * v1.w;
            }
        }
    }

    float linv[4];
#pragma unroll
    for (int i = 0; i < 4; i++) linv[i] = 1.f / lrow[tr * 4 + i];
#pragma unroll
    for (int i = 0; i < 4; i++) {
        size_t base = ((size_t)(qb * BQ + tr * 4 + i) * NH + h) * HD + tc * 8;
#pragma unroll
        for (int j = 0; j < 8; j++) g_ctx[base + j] = o[i][j] * linv[i];
    }
}

// ---------------------------------------------------------------------------
// Launch
// ---------------------------------------------------------------------------
extern "C" void kernel_launch(void* const* d_in, const int* in_sizes, int n_in,
                              void* d_out, int out_size) {
    const float* hs   = (const float*)d_in[0];  // [1,4096,2048]
    const float* cosb = (const float*)d_in[1];  // [4096,32]
    const float* sinb = (const float*)d_in[2];  // [4096,32]
    // d_in[3] = attention_mask (pure causal, applied analytically)
    const float* wq = (const float*)d_in[4];    // [2048,4096]
    const float* wk = (const float*)d_in[5];    // [2048,512]
    const float* wv = (const float*)d_in[6];    // [2048,512]
    const float* wo = (const float*)d_in[7];    // [4096,2048]

    float* out   = (float*)d_out;
    float* out_o = out;                                    // [4096,2048]
    float* out_k = out + (size_t)SEQ * HIDDEN;             // [4096,2,256]
    float* out_v = out_k + (size_t)SEQ * NKV * HD;         // [4096,2,256]

    float *qp, *kp, *vp, *cp;
    cudaGetSymbolAddress((void**)&qp, g_q);
    cudaGetSymbolAddress((void**)&kp, g_k);
    cudaGetSymbolAddress((void**)&vp, g_v);
    cudaGetSymbolAddress((void**)&cp, g_ctx);
    __nv_bfloat16 *hsh, *hsl, *ctxh, *ctxl, *wqth, *wqtl, *wkth, *wktl, *wvth, *wvtl, *woth, *wotl;
    cudaGetSymbolAddress((void**)&hsh, g_hsh);   cudaGetSymbolAddress((void**)&hsl, g_hsl);
    cudaGetSymbolAddress((void**)&ctxh, g_ctxh); cudaGetSymbolAddress((void**)&ctxl, g_ctxl);
    cudaGetSymbolAddress((void**)&wqth, g_wqth); cudaGetSymbolAddress((void**)&wqtl, g_wqtl);
    cudaGetSymbolAddress((void**)&wkth, g_wkth); cudaGetSymbolAddress((void**)&wktl, g_wktl);
    cudaGetSymbolAddress((void**)&wvth, g_wvth); cudaGetSymbolAddress((void**)&wvtl, g_wvtl);
    cudaGetSymbolAddress((void**)&woth, g_woth); cudaGetSymbolAddress((void**)&wotl, g_wotl);

    // Prep: split activations, transpose+split weights
    split_hi_lo<<<(SEQ * HIDDEN / 4) / 256, 256>>>(hs, hsh, hsl);
    transpose_split<<<dim3((NH * HD) / 32, HIDDEN / 32), 256>>>(wq, wqth, wqtl, HIDDEN, NH * HD);
    transpose_split<<<dim3((NKV * HD) / 32, HIDDEN / 32), 256>>>(wk, wkth, wktl, HIDDEN, NKV * HD);
    transpose_split<<<dim3((NKV * HD) / 32, HIDDEN / 32), 256>>>(wv, wvth, wvtl, HIDDEN, NKV * HD);
    transpose_split<<<dim3(HIDDEN / 32, (NH * HD) / 32), 256>>>(wo, woth, wotl, NH * HD, HIDDEN);

    // Projections on tensor cores (bf16x3 via mma.sync)
    gemm_mma<<<dim3((NH * HD) / 128, SEQ / 128), 256>>>(hsh, hsl, wqth, wqtl, qp, SEQ, NH * HD, HIDDEN);
    gemm_mma<<<dim3((NKV * HD) / 128, SEQ / 128), 256>>>(hsh, hsl, wkth, wktl, kp, SEQ, NKV * HD, HIDDEN);
    gemm_mma<<<dim3((NKV * HD) / 128, SEQ / 128), 256>>>(hsh, hsl, wvth, wvtl, vp, SEQ, NKV * HD, HIDDEN);

    // RoPE on Q; fused RoPE+copy for K, copy for V
    rope_q_kernel<<<(SEQ * NH * RHALF) / 256, 256>>>(cosb, sinb);
    rope_copy_k_v_kernel<<<(SEQ * NKV * 128) / 256, 256>>>(cosb, sinb, out_k, out_v);

    // Attention
    size_t smem = (size_t)(BQ * QSTR + BKEY * KSTR + BKEY * VSTR + BQ * SSTR + 3 * BQ) * sizeof(float);
    cudaFuncSetAttribute(attn_kernel, cudaFuncAttributeMaxDynamicSharedMemorySize, (int)smem);
    attn_kernel<<<dim3(SEQ / BQ, NH), 256, smem>>>(0.0625f);  // 256^-0.5

    // Output projection on tensor cores
    split_hi_lo<<<((size_t)SEQ * NH * HD / 4) / 256, 256>>>(cp, ctxh, ctxl);
    gemm_mma<<<dim3(HIDDEN / 128, SEQ / 128), 256>>>(ctxh, ctxl, woth, wotl, out_o, SEQ, HIDDEN, NH * HD);
}

// round 10
// speedup vs baseline: 2.8025x; 2.2839x over previous
#include <cuda_runtime.h>
#include <cuda_bf16.h>
#include <cstdint>

#define SEQ    4096
#define HIDDEN 2048
#define NH     16
#define NKV    2
#define HD     256
#define RHALF  32
#define GQ     (NH / NKV)

// ---------------------------------------------------------------------------
// Scratch (device globals — no allocations allowed)
// ---------------------------------------------------------------------------
__device__ float g_q[(size_t)SEQ * NH * HD];       // 64 MB
__device__ float g_k[(size_t)SEQ * NKV * HD];      // 8 MB
__device__ float g_v[(size_t)SEQ * NKV * HD];      // 8 MB

// bf16 hi/lo split operands
__device__ __nv_bfloat16 g_hsh[(size_t)SEQ * HIDDEN];
__device__ __nv_bfloat16 g_hsl[(size_t)SEQ * HIDDEN];
__device__ __nv_bfloat16 g_qh[(size_t)SEQ * NH * HD];
__device__ __nv_bfloat16 g_ql[(size_t)SEQ * NH * HD];
__device__ __nv_bfloat16 g_kh[(size_t)SEQ * NKV * HD];
__device__ __nv_bfloat16 g_kl[(size_t)SEQ * NKV * HD];
__device__ __nv_bfloat16 g_vth[(size_t)NKV * HD * SEQ];   // [kvh][d][s]
__device__ __nv_bfloat16 g_vtl[(size_t)NKV * HD * SEQ];
__device__ __nv_bfloat16 g_ctxh[(size_t)SEQ * NH * HD];   // attention out (hi/lo)
__device__ __nv_bfloat16 g_ctxl[(size_t)SEQ * NH * HD];
__device__ __nv_bfloat16 g_wqth[(size_t)(NH * HD) * HIDDEN];
__device__ __nv_bfloat16 g_wqtl[(size_t)(NH * HD) * HIDDEN];
__device__ __nv_bfloat16 g_wkth[(size_t)(NKV * HD) * HIDDEN];
__device__ __nv_bfloat16 g_wktl[(size_t)(NKV * HD) * HIDDEN];
__device__ __nv_bfloat16 g_wvth[(size_t)(NKV * HD) * HIDDEN];
__device__ __nv_bfloat16 g_wvtl[(size_t)(NKV * HD) * HIDDEN];
__device__ __nv_bfloat16 g_woth[(size_t)HIDDEN * (NH * HD)];
__device__ __nv_bfloat16 g_wotl[(size_t)HIDDEN * (NH * HD)];

// ---------------------------------------------------------------------------
// mma.sync m16n8k16 bf16 -> fp32 (baseline-PTX tensor path; verified in R9)
// ---------------------------------------------------------------------------
__device__ __forceinline__ void mma16816(float c[4],
                                         uint32_t a0, uint32_t a1, uint32_t a2, uint32_t a3,
                                         uint32_t b0, uint32_t b1) {
    asm volatile(
        "mma.sync.aligned.m16n8k16.row.col.f32.bf16.bf16.f32 "
        "{%0,%1,%2,%3}, {%4,%5,%6,%7}, {%8,%9}, {%0,%1,%2,%3};"
        : "+f"(c[0]), "+f"(c[1]), "+f"(c[2]), "+f"(c[3])
        : "r"(a0), "r"(a1), "r"(a2), "r"(a3), "r"(b0), "r"(b1));
}

__device__ __forceinline__ uint32_t pack2bf16(float a, float b) {
    __nv_bfloat162 t = __floats2bfloat162_rn(a, b);
    return *(uint32_t*)&t;
}

// ---------------------------------------------------------------------------
// Prep kernels
// ---------------------------------------------------------------------------
__global__ void __launch_bounds__(256) split_hi_lo(const float* __restrict__ x,
                                                   __nv_bfloat16* __restrict__ hi,
                                                   __nv_bfloat16* __restrict__ lo) {
    int i = blockIdx.x * 256 + threadIdx.x;
    float4 v = ((const float4*)x)[i];
    __nv_bfloat16 h0 = __float2bfloat16(v.x), h1 = __float2bfloat16(v.y);
    __nv_bfloat16 h2 = __float2bfloat16(v.z), h3 = __float2bfloat16(v.w);
    uint2 hp, lp;
    hp.x = pack2bf16(v.x, v.y); hp.y = pack2bf16(v.z, v.w);
    lp.x = pack2bf16(v.x - __bfloat162float(h0), v.y - __bfloat162float(h1));
    lp.y = pack2bf16(v.z - __bfloat162float(h2), v.w - __bfloat162float(h3));
    ((uint2*)hi)[i] = hp;
    ((uint2*)lo)[i] = lp;
}

// W [K][N] fp32 -> WT_hi/lo [N][K] bf16 (32x32 smem tile transpose)
__global__ void __launch_bounds__(256) transpose_split(const float* __restrict__ w,
                                                       __nv_bfloat16* __restrict__ th,
                                                       __nv_bfloat16* __restrict__ tl,
                                                       int K, int N) {
    __shared__ float tile[32][33];
    int n0 = blockIdx.x * 32, k0 = blockIdx.y * 32;
    int tx = threadIdx.x & 31, ty = threadIdx.x >> 5;
#pragma unroll
    for (int i = 0; i < 32; i += 8)
        tile[ty + i][tx] = w[(size_t)(k0 + ty + i) * N + n0 + tx];
    __syncthreads();
#pragma unroll
    for (int i = 0; i < 32; i += 8) {
        float v = tile[tx][ty + i];
        __nv_bfloat16 h = __float2bfloat16(v);
        __nv_bfloat16 l = __float2bfloat16(v - __bfloat162float(h));
        size_t o = (size_t)(n0 + ty + i) * K + k0 + tx;
        th[o] = h;
        tl[o] = l;
    }
}

// g_v [s][kvh][d] fp32 -> g_vth/g_vtl [kvh][d][s] bf16
__global__ void __launch_bounds__(256) vt_split() {
    __shared__ float tile[32][33];
    int s0 = blockIdx.x * 32, d0 = blockIdx.y * 32, kvh = blockIdx.z;
    int tx = threadIdx.x & 31, ty = threadIdx.x >> 5;
#pragma unroll
    for (int i = 0; i < 32; i += 8)
        tile[ty + i][tx] = g_v[((size_t)(s0 + ty + i) * NKV + kvh) * HD + d0 + tx];
    __syncthreads();
#pragma unroll
    for (int i = 0; i < 32; i += 8) {
        float v = tile[tx][ty + i];   // = v[s0+tx][d0+ty+i]
        __nv_bfloat16 h = __float2bfloat16(v);
        __nv_bfloat16 l = __float2bfloat16(v - __bfloat162float(h));
        size_t o = ((size_t)kvh * HD + d0 + ty + i) * SEQ + s0 + tx;
        g_vth[o] = h;
        g_vtl[o] = l;
    }
}

// ---------------------------------------------------------------------------
// Tensor-core bf16x3 GEMM via mma.sync (unchanged from R9 — verified)
// ---------------------------------------------------------------------------
#define ASTR 40

__global__ void __launch_bounds__(256) gemm_mma(
    const __nv_bfloat16* __restrict__ Ah, const __nv_bfloat16* __restrict__ Al,
    const __nv_bfloat16* __restrict__ Bh, const __nv_bfloat16* __restrict__ Bl,
    float* __restrict__ C, int M, int N, int K)
{
    __shared__ __nv_bfloat16 sAh[128 * ASTR];
    __shared__ __nv_bfloat16 sAl[128 * ASTR];
    __shared__ __nv_bfloat16 sBh[128 * ASTR];
    __shared__ __nv_bfloat16 sBl[128 * ASTR];

    int tid = threadIdx.x;
    int wid = tid >> 5, lane = tid & 31;
    int gr = lane >> 2, q = lane & 3;
    int warp_m = (wid >> 2) * 64;
    int warp_n = (wid & 3) * 32;
    int m0 = blockIdx.y * 128, n0 = blockIdx.x * 128;

    float acc[4][4][4];
#pragma unroll
    for (int mt = 0; mt < 4; mt++)
#pragma unroll
        for (int nt = 0; nt < 4; nt++)
#pragma unroll
            for (int r = 0; r < 4; r++) acc[mt][nt][r] = 0.f;

    for (int k0 = 0; k0 < K; k0 += 32) {
#pragma unroll
        for (int i = 0; i < 2; i++) {
            int ch = tid + i * 256;
            int r = ch >> 2, c = (ch & 3) << 3;
            int so = r * ASTR + c;
            *(uint4*)(sAh + so) = *(const uint4*)(Ah + (size_t)(m0 + r) * K + k0 + c);
            *(uint4*)(sAl + so) = *(const uint4*)(Al + (size_t)(m0 + r) * K + k0 + c);
            *(uint4*)(sBh + so) = *(const uint4*)(Bh + (size_t)(n0 + r) * K + k0 + c);
            *(uint4*)(sBl + so) = *(const uint4*)(Bl + (size_t)(n0 + r) * K + k0 + c);
        }
        __syncthreads();

#pragma unroll
        for (int ks = 0; ks < 2; ks++) {
            int kb = ks * 16 + 2 * q;
            uint32_t ah[4][4], al[4][4];
#pragma unroll
            for (int mt = 0; mt < 4; mt++) {
                int row = warp_m + mt * 16 + gr;
                const __nv_bfloat16* bh_ = sAh + row * ASTR + kb;
                const __nv_bfloat16* bl_ = sAl + row * ASTR + kb;
                ah[mt][0] = *(const uint32_t*)bh_;
                ah[mt][1] = *(const uint32_t*)(bh_ + 8 * ASTR);
                ah[mt][2] = *(const uint32_t*)(bh_ + 8);
                ah[mt][3] = *(const uint32_t*)(bh_ + 8 * ASTR + 8);
                al[mt][0] = *(const uint32_t*)bl_;
                al[mt][1] = *(const uint32_t*)(bl_ + 8 * ASTR);
                al[mt][2] = *(const uint32_t*)(bl_ + 8);
                al[mt][3] = *(const uint32_t*)(bl_ + 8 * ASTR + 8);
            }
#pragma unroll
            for (int nt = 0; nt < 4; nt++) {
                int col = warp_n + nt * 8 + gr;
                const __nv_bfloat16* pbh = sBh + col * ASTR + kb;
                const __nv_bfloat16* pbl = sBl + col * ASTR + kb;
                uint32_t bh0 = *(const uint32_t*)pbh;
                uint32_t bh1 = *(const uint32_t*)(pbh + 8);
                uint32_t bl0 = *(const uint32_t*)pbl;
                uint32_t bl1 = *(const uint32_t*)(pbl + 8);
#pragma unroll
                for (int mt = 0; mt < 4; mt++) {
                    mma16816(acc[mt][nt], ah[mt][0], ah[mt][1], ah[mt][2], ah[mt][3], bh0, bh1);
                    mma16816(acc[mt][nt], ah[mt][0], ah[mt][1], ah[mt][2], ah[mt][3], bl0, bl1);
                    mma16816(acc[mt][nt], al[mt][0], al[mt][1], al[mt][2], al[mt][3], bh0, bh1);
                }
            }
        }
        __syncthreads();
    }

#pragma unroll
    for (int mt = 0; mt < 4; mt++) {
#pragma unroll
        for (int nt = 0; nt < 4; nt++) {
            int row = m0 + warp_m + mt * 16 + gr;
            int col = n0 + warp_n + nt * 8 + 2 * q;
            *(float2*)(C + (size_t)row * N + col) = make_float2(acc[mt][nt][0], acc[mt][nt][1]);
            *(float2*)(C + (size_t)(row + 8) * N + col) = make_float2(acc[mt][nt][2], acc[mt][nt][3]);
        }
    }
}

// ---------------------------------------------------------------------------
// RoPE kernels (fp32, unchanged)
// ---------------------------------------------------------------------------
__global__ void rope_q_kernel(const float* __restrict__ cosb,
                              const float* __restrict__ sinb) {
    int idx = blockIdx.x * 256 + threadIdx.x;
    int i = idx & 31;
    int h = (idx >> 5) & (NH - 1);
    int s = idx >> 9;
    float c = cosb[s * RHALF + i];
    float sn = sinb[s * RHALF + i];
    float* p = g_q + ((size_t)s * NH + h) * HD;
    float x1 = p[i], x2 = p[i + RHALF];
    p[i] = x1 * c - x2 * sn;
    p[i + RHALF] = x1 * sn + x2 * c;
}

__global__ void rope_copy_k_v_kernel(const float* __restrict__ cosb,
                                     const float* __restrict__ sinb,
                                     float* __restrict__ out_k,
                                     float* __restrict__ out_v) {
    int idx = blockIdx.x * 256 + threadIdx.x;
    int t = idx & 127;
    int row = idx >> 7;
    int s = row >> 1;
    size_t base = (size_t)row * HD;
    float* kp = g_k + base;
    float* ok = out_k + base;

    if (t < 32) {
        float c = cosb[s * RHALF + t];
        float sn = sinb[s * RHALF + t];
        float x1 = kp[t], x2 = kp[t + RHALF];
        float r1 = x1 * c - x2 * sn;
        float r2 = x1 * sn + x2 * c;
        kp[t] = r1; kp[t + RHALF] = r2;
        ok[t] = r1; ok[t + RHALF] = r2;
    } else {
        int d = 64 + (t - 32) * 2;
        float2 x = *(const float2*)(kp + d);
        *(float2*)(ok + d) = x;
    }
    float2 v = *(const float2*)(g_v + base + t * 2);
    *(float2*)(out_v + base + t * 2) = v;
}

// ---------------------------------------------------------------------------
// Tensor-core flash attention (bf16x3), causal. BQ=64, BKEY=64.
// Grid (SEQ/64, NH), 256 threads (8 warps: mt = wid>>1, nh = wid&1).
// Writes ctx hi/lo bf16 directly (feeds wo GEMM).
// ---------------------------------------------------------------------------
#define QKS   264   // Q/K tile stride (bf16): 256 + 8
#define VTS2  72    // Vt tile stride (bf16): 64 + 8
#define PSTR2 72
#define SSTR2 66

#define OFF_QH 0
#define OFF_QL 33792
#define OFF_KH 67584
#define OFF_KL 101376
#define OFF_VH 135168
#define OFF_VL 172032
#define OFF_PS 208896
#define OFF_ST 227328
#define ATT_SMEM 228096

__global__ void __launch_bounds__(256, 1) attn_mma(float scale) {
    extern __shared__ char smc[];
    __nv_bfloat16* sQh = (__nv_bfloat16*)(smc + OFF_QH);
    __nv_bfloat16* sQl = (__nv_bfloat16*)(smc + OFF_QL);
    __nv_bfloat16* sKh = (__nv_bfloat16*)(smc + OFF_KH);
    __nv_bfloat16* sKl = (__nv_bfloat16*)(smc + OFF_KL);
    __nv_bfloat16* sVh = (__nv_bfloat16*)(smc + OFF_VH);
    __nv_bfloat16* sVl = (__nv_bfloat16*)(smc + OFF_VL);
    float* sS = (float*)(smc + OFF_PS);              // unioned with Ph/Pl
    __nv_bfloat16* sPh = (__nv_bfloat16*)(smc + OFF_PS);
    __nv_bfloat16* sPl = sPh + 64 * PSTR2;
    float* mrow = (float*)(smc + OFF_ST);
    float* lrow = mrow + 64;
    float* arow = lrow + 64;

    int qb = blockIdx.x, h = blockIdx.y, kvh = h / GQ;
    int tid = threadIdx.x, wid = tid >> 5, lane = tid & 31;
    int gr = lane >> 2, q = lane & 3;
    int mt = wid >> 1;          // 0..3: 16-row m-tile
    int nh = wid & 1;           // S col-half / O dim-half
    int row0 = mt * 16 + gr;

    // Load Q tiles [64][256] hi/lo
    for (int t = tid; t < 2048; t += 256) {
        int r = t >> 5, c = (t & 31) << 3;
        size_t g = ((size_t)(qb * 64 + r) * NH + h) * HD + c;
        *(uint4*)(sQh + r * QKS + c) = *(const uint4*)(g_qh + g);
        *(uint4*)(sQl + r * QKS + c) = *(const uint4*)(g_ql + g);
    }
    if (tid < 64) { mrow[tid] = -1e30f; lrow[tid] = 0.f; }

    float o[16][4];
#pragma unroll
    for (int nt = 0; nt < 16; nt++)
#pragma unroll
        for (int r = 0; r < 4; r++) o[nt][r] = 0.f;

    int nkb = qb + 1;
    for (int kb = 0; kb < nkb; kb++) {
        __syncthreads();  // prev iter's PV reads done before overwriting K/V
        for (int t = tid; t < 2048; t += 256) {
            int r = t >> 5, c = (t & 31) << 3;
            size_t g = ((size_t)(kb * 64 + r) * NKV + kvh) * HD + c;
            *(uint4*)(sKh + r * QKS + c) = *(const uint4*)(g_kh + g);
            *(uint4*)(sKl + r * QKS + c) = *(const uint4*)(g_kl + g);
        }
        for (int t = tid; t < 2048; t += 256) {
            int r = t >> 3, c = (t & 7) << 3;
            size_t g = ((size_t)kvh * HD + r) * SEQ + kb * 64 + c;
            *(uint4*)(sVh + r * VTS2 + c) = *(const uint4*)(g_vth + g);
            *(uint4*)(sVl + r * VTS2 + c) = *(const uint4*)(g_vtl + g);
        }
        __syncthreads();

        // ---- S = Q K^T (m16 x n32 per warp), bf16x3 ----
        float sacc[4][4];
#pragma unroll
        for (int nt = 0; nt < 4; nt++)
#pragma unroll
            for (int r = 0; r < 4; r++) sacc[nt][r] = 0.f;

#pragma unroll 4
        for (int ks = 0; ks < 16; ks++) {
            int kk = ks * 16 + 2 * q;
            const __nv_bfloat16* qh_ = sQh + row0 * QKS + kk;
            const __nv_bfloat16* ql_ = sQl + row0 * QKS + kk;
            uint32_t ah0 = *(const uint32_t*)qh_;
            uint32_t ah1 = *(const uint32_t*)(qh_ + 8 * QKS);
            uint32_t ah2 = *(const uint32_t*)(qh_ + 8);
            uint32_t ah3 = *(const uint32_t*)(qh_ + 8 * QKS + 8);
            uint32_t al0 = *(const uint32_t*)ql_;
            uint32_t al1 = *(const uint32_t*)(ql_ + 8 * QKS);
            uint32_t al2 = *(const uint32_t*)(ql_ + 8);
            uint32_t al3 = *(const uint32_t*)(ql_ + 8 * QKS + 8);
#pragma unroll
            for (int nt = 0; nt < 4; nt++) {
                int col = nh * 32 + nt * 8 + gr;
                const __nv_bfloat16* kh_ = sKh + col * QKS + kk;
                const __nv_bfloat16* kl_ = sKl + col * QKS + kk;
                uint32_t bh0 = *(const uint32_t*)kh_;
                uint32_t bh1 = *(const uint32_t*)(kh_ + 8);
                uint32_t bl0 = *(const uint32_t*)kl_;
                uint32_t bl1 = *(const uint32_t*)(kl_ + 8);
                mma16816(sacc[nt], ah0, ah1, ah2, ah3, bh0, bh1);
                mma16816(sacc[nt], ah0, ah1, ah2, ah3, bl0, bl1);
                mma16816(sacc[nt], al0, al1, al2, al3, bh0, bh1);
            }
        }
        // masked*scaled scores -> sS
        int rg0 = qb * 64 + row0, rg1 = rg0 + 8;
#pragma unroll
        for (int nt = 0; nt < 4; nt++) {
            int cl = nh * 32 + nt * 8 + 2 * q;
            int cg = kb * 64 + cl;
            sS[row0 * SSTR2 + cl]           = (cg     <= rg0) ? sacc[nt][0] * scale : -1e30f;
            sS[row0 * SSTR2 + cl + 1]       = (cg + 1 <= rg0) ? sacc[nt][1] * scale : -1e30f;
            sS[(row0 + 8) * SSTR2 + cl]     = (cg     <= rg1) ? sacc[nt][2] * scale : -1e30f;
            sS[(row0 + 8) * SSTR2 + cl + 1] = (cg + 1 <= rg1) ? sacc[nt][3] * scale : -1e30f;
        }
        __syncthreads();

        // ---- online softmax: 4 threads per row, 16 cols each ----
        int srow = tid >> 2, sub = tid & 3;
        float sv[16];
        float mx = -1e30f;
#pragma unroll
        for (int j = 0; j < 16; j++) {
            sv[j] = sS[srow * SSTR2 + sub * 16 + j];
            mx = fmaxf(mx, sv[j]);
        }
        mx = fmaxf(mx, __shfl_xor_sync(0xffffffffu, mx, 1));
        mx = fmaxf(mx, __shfl_xor_sync(0xffffffffu, mx, 2));
        float m_old = mrow[srow];
        float mnew = fmaxf(m_old, mx);
        float al = __expf(m_old - mnew);
        float lsum = 0.f;
#pragma unroll
        for (int j = 0; j < 16; j++) {
            sv[j] = __expf(sv[j] - mnew);
            lsum += sv[j];
        }
        lsum += __shfl_xor_sync(0xffffffffu, lsum, 1);
        lsum += __shfl_xor_sync(0xffffffffu, lsum, 2);
        if (sub == 0) {
            mrow[srow] = mnew;
            arow[srow] = al;
            lrow[srow] = lrow[srow] * al + lsum;
        }
        __syncthreads();  // all S reads complete before P overwrites the region

        // write P hi/lo (bf16x2 split of probs)
#pragma unroll
        for (int j = 0; j < 16; j += 2) {
            float p0 = sv[j], p1 = sv[j + 1];
            __nv_bfloat16 h0 = __float2bfloat16(p0);
            __nv_bfloat16 h1 = __float2bfloat16(p1);
            uint32_t hp = pack2bf16(p0, p1);
            uint32_t lp = pack2bf16(p0 - __bfloat162float(h0), p1 - __bfloat162float(h1));
            *(uint32_t*)(sPh + srow * PSTR2 + sub * 16 + j) = hp;
            *(uint32_t*)(sPl + srow * PSTR2 + sub * 16 + j) = lp;
        }

        // rescale O accumulators
        float a0 = arow[row0], a1 = arow[row0 + 8];
#pragma unroll
        for (int nt = 0; nt < 16; nt++) {
            o[nt][0] *= a0; o[nt][1] *= a0;
            o[nt][2] *= a1; o[nt][3] *= a1;
        }
        __syncthreads();  // P visible to all warps

        // ---- O += P @ V (m16 x n128 per warp), bf16x3 ----
#pragma unroll
        for (int ks = 0; ks < 4; ks++) {
            int kk = ks * 16 + 2 * q;
            const __nv_bfloat16* ph_ = sPh + row0 * PSTR2 + kk;
            const __nv_bfloat16* pl_ = sPl + row0 * PSTR2 + kk;
            uint32_t ah0 = *(const uint32_t*)ph_;
            uint32_t ah1 = *(const uint32_t*)(ph_ + 8 * PSTR2);
            uint32_t ah2 = *(const uint32_t*)(ph_ + 8);
            uint32_t ah3 = *(const uint32_t*)(ph_ + 8 * PSTR2 + 8);
            uint32_t al0 = *(const uint32_t*)pl_;
            uint32_t al1 = *(const uint32_t*)(pl_ + 8 * PSTR2);
            uint32_t al2 = *(const uint32_t*)(pl_ + 8);
            uint32_t al3 = *(const uint32_t*)(pl_ + 8 * PSTR2 + 8);
#pragma unroll
            for (int nt = 0; nt < 16; nt++) {
                int drow = nh * 128 + nt * 8 + gr;
                const __nv_bfloat16* vh_ = sVh + drow * VTS2 + kk;
                const __nv_bfloat16* vl_ = sVl + drow * VTS2 + kk;
                uint32_t bh0 = *(const uint32_t*)vh_;
                uint32_t bh1 = *(const uint32_t*)(vh_ + 8);
                uint32_t bl0 = *(const uint32_t*)vl_;
                uint32_t bl1 = *(const uint32_t*)(vl_ + 8);
                mma16816(o[nt], ah0, ah1, ah2, ah3, bh0, bh1);
                mma16816(o[nt], ah0, ah1, ah2, ah3, bl0, bl1);
                mma16816(o[nt], al0, al1, al2, al3, bh0, bh1);
            }
        }
    }

    __syncthreads();
    float li0 = 1.f / lrow[row0], li1 = 1.f / lrow[row0 + 8];
#pragma unroll
    for (int nt = 0; nt < 16; nt++) {
        int col = nh * 128 + nt * 8 + 2 * q;
        size_t b0 = ((size_t)(qb * 64 + row0) * NH + h) * HD + col;
        size_t b1 = ((size_t)(qb * 64 + row0 + 8) * NH + h) * HD + col;
        float v0 = o[nt][0] * li0, v1 = o[nt][1] * li0;
        float v2 = o[nt][2] * li1, v3 = o[nt][3] * li1;
        __nv_bfloat16 h0 = __float2bfloat16(v0), h1 = __float2bfloat16(v1);
        __nv_bfloat16 h2 = __float2bfloat16(v2), h3 = __float2bfloat16(v3);
        *(uint32_t*)(g_ctxh + b0) = pack2bf16(v0, v1);
        *(uint32_t*)(g_ctxh + b1) = pack2bf16(v2, v3);
        *(uint32_t*)(g_ctxl + b0) = pack2bf16(v0 - __bfloat162float(h0), v1 - __bfloat162float(h1));
        *(uint32_t*)(g_ctxl + b1) = pack2bf16(v2 - __bfloat162float(h2), v3 - __bfloat162float(h3));
    }
}

// ---------------------------------------------------------------------------
// Launch
// ---------------------------------------------------------------------------
extern "C" void kernel_launch(void* const* d_in, const int* in_sizes, int n_in,
                              void* d_out, int out_size) {
    const float* hs   = (const float*)d_in[0];
    const float* cosb = (const float*)d_in[1];
    const float* sinb = (const float*)d_in[2];
    // d_in[3] = attention_mask (pure causal, applied analytically)
    const float* wq = (const float*)d_in[4];
    const float* wk = (const float*)d_in[5];
    const float* wv = (const float*)d_in[6];
    const float* wo = (const float*)d_in[7];

    float* out   = (float*)d_out;
    float* out_o = out;
    float* out_k = out + (size_t)SEQ * HIDDEN;
    float* out_v = out_k + (size_t)SEQ * NKV * HD;

    float *qp, *kp, *vp;
    cudaGetSymbolAddress((void**)&qp, g_q);
    cudaGetSymbolAddress((void**)&kp, g_k);
    cudaGetSymbolAddress((void**)&vp, g_v);
    __nv_bfloat16 *hsh, *hsl, *qh, *ql, *kh, *kl, *ctxh, *ctxl;
    __nv_bfloat16 *wqth, *wqtl, *wkth, *wktl, *wvth, *wvtl, *woth, *wotl;
    cudaGetSymbolAddress((void**)&hsh, g_hsh);   cudaGetSymbolAddress((void**)&hsl, g_hsl);
    cudaGetSymbolAddress((void**)&qh, g_qh);     cudaGetSymbolAddress((void**)&ql, g_ql);
    cudaGetSymbolAddress((void**)&kh, g_kh);     cudaGetSymbolAddress((void**)&kl, g_kl);
    cudaGetSymbolAddress((void**)&ctxh, g_ctxh); cudaGetSymbolAddress((void**)&ctxl, g_ctxl);
    cudaGetSymbolAddress((void**)&wqth, g_wqth); cudaGetSymbolAddress((void**)&wqtl, g_wqtl);
    cudaGetSymbolAddress((void**)&wkth, g_wkth); cudaGetSymbolAddress((void**)&wktl, g_wktl);
    cudaGetSymbolAddress((void**)&wvth, g_wvth); cudaGetSymbolAddress((void**)&wvtl, g_wvtl);
    cudaGetSymbolAddress((void**)&woth, g_woth); cudaGetSymbolAddress((void**)&wotl, g_wotl);

    // Prep: split activations, transpose+split weights
    split_hi_lo<<<(SEQ * HIDDEN / 4) / 256, 256>>>(hs, hsh, hsl);
    transpose_split<<<dim3((NH * HD) / 32, HIDDEN / 32), 256>>>(wq, wqth, wqtl, HIDDEN, NH * HD);
    transpose_split<<<dim3((NKV * HD) / 32, HIDDEN / 32), 256>>>(wk, wkth, wktl, HIDDEN, NKV * HD);
    transpose_split<<<dim3((NKV * HD) / 32, HIDDEN / 32), 256>>>(wv, wvth, wvtl, HIDDEN, NKV * HD);
    transpose_split<<<dim3(HIDDEN / 32, (NH * HD) / 32), 256>>>(wo, woth, wotl, NH * HD, HIDDEN);

    // Projections on tensor cores (bf16x3 via mma.sync)
    gemm_mma<<<dim3((NH * HD) / 128, SEQ / 128), 256>>>(hsh, hsl, wqth, wqtl, qp, SEQ, NH * HD, HIDDEN);
    gemm_mma<<<dim3((NKV * HD) / 128, SEQ / 128), 256>>>(hsh, hsl, wkth, wktl, kp, SEQ, NKV * HD, HIDDEN);
    gemm_mma<<<dim3((NKV * HD) / 128, SEQ / 128), 256>>>(hsh, hsl, wvth, wvtl, vp, SEQ, NKV * HD, HIDDEN);

    // RoPE on Q; fused RoPE+copy for K, copy for V
    rope_q_kernel<<<(SEQ * NH * RHALF) / 256, 256>>>(cosb, sinb);
    rope_copy_k_v_kernel<<<(SEQ * NKV * 128) / 256, 256>>>(cosb, sinb, out_k, out_v);

    // hi/lo splits for attention operands
    split_hi_lo<<<((size_t)SEQ * NH * HD / 4) / 256, 256>>>(qp, qh, ql);
    split_hi_lo<<<((size_t)SEQ * NKV * HD / 4) / 256, 256>>>(kp, kh, kl);
    vt_split<<<dim3(SEQ / 32, HD / 32, NKV), 256>>>();

    // Tensor-core flash attention (writes ctx hi/lo directly)
    cudaFuncSetAttribute(attn_mma, cudaFuncAttributeMaxDynamicSharedMemorySize, ATT_SMEM);
    attn_mma<<<dim3(SEQ / 64, NH), 256, ATT_SMEM>>>(0.0625f);  // 256^-0.5

    // Output projection on tensor cores
    gemm_mma<<<dim3(HIDDEN / 128, SEQ / 128), 256>>>(ctxh, ctxl, woth, wotl, out_o, SEQ, HIDDEN, NH * HD);
}